// round 17
// baseline (speedup 1.0000x reference)
#include <cuda_runtime.h>
#include <cuda_bf16.h>

#define NNODES 100000
#define NEDGES 1600000
#define DH 128
#define DOUT 64
#define BN_EPS 1e-5f

#define TM 64
#define GEMM_THREADS 256
#define XS_STRIDE 132                 // 64 rows  (A tile), bank-spread pad
#define WS_STRIDE 136                 // 128 rows (B tile), bank-spread pad
#define GEMM_SMEM ((DH * WS_STRIDE + TM * XS_STRIDE) * 4)   // ~103.4 KB
#define GRID_GEMM ((NNODES + TM - 1) / TM)                  // 1563
// fat grid: groups of 8 blocks = 7 gemm + 1 hist (interleaved for concurrency)
#define FAT_GROUPS ((GRID_GEMM + 6) / 7)                    // 224
#define FAT_GRID (FAT_GROUPS * 8)                           // 1792
#define FILL_BLOCKS ((NEDGES + 255) / 256)

// ---------------- device scratch ----------------
struct alignas(8) Edge { int s; float w; };

__device__ __nv_bfloat16 g_hb[(long)NNODES * DH];    // GEMM output (bf16)
__device__ __nv_bfloat16 g_aggb[(long)NNODES * DH];  // aggregation (bf16)
__device__ float g_s[NNODES];                // per-src edge-weight sums
__device__ float g_stats[2][2 * DH];         // per-layer column sum / sumsq
__device__ float g_t[DH];                    // s^T x1
__device__ int   g_rowptr[NNODES];           // CSR segment begin (by dst)
__device__ int   g_cnt[NNODES];              // histogram / cursor / seg end
__device__ int   g_total;                    // segment allocator
__device__ Edge  g_csr[NEDGES];              // packed (src, weight)

__device__ __forceinline__ unsigned tf32_of(float f) {
    unsigned r;
    asm("cvt.rna.tf32.f32 %0, %1;" : "=r"(r) : "f"(f));
    return r;
}

#define MMA_TF32(d, a, b)                                                    \
    asm volatile(                                                            \
        "mma.sync.aligned.m16n8k8.row.col.f32.tf32.tf32.f32 "                \
        "{%0,%1,%2,%3}, {%4,%5,%6,%7}, {%8,%9}, {%0,%1,%2,%3};"              \
        : "+f"((d)[0]), "+f"((d)[1]), "+f"((d)[2]), "+f"((d)[3])             \
        : "r"((a)[0]), "r"((a)[1]), "r"((a)[2]), "r"((a)[3]),                \
          "r"((b)[0]), "r"((b)[1]))

// ---------------- init: counters, s, stats, t, allocator --------------------
__global__ void zero_init_kernel() {
    int i = blockIdx.x * blockDim.x + threadIdx.x;
    int stride = gridDim.x * blockDim.x;
    for (int j = i; j < NNODES; j += stride) { g_cnt[j] = 0; g_s[j] = 0.f; }
    if (i < 4 * DH)       ((float*)g_stats)[i] = 0.f;
    else if (i < 5 * DH)  g_t[i - 4 * DH] = 0.f;
    if (i == 5 * DH)      g_total = 0;
}

// ---------------- GEMM body: g_hb = X @ W via TF32 tensor-core mma ----------
// mode 0: X = Xext (fp32 raw); mode 1: X = relu(bn0(g_aggb)) with inline BN
__device__ __forceinline__ void gemm_body(const float* __restrict__ Xext,
                                          const float* __restrict__ W,
                                          int mode, int blk,
                                          const float* __restrict__ gamma,
                                          const float* __restrict__ beta) {
    extern __shared__ unsigned smem_u[];
    unsigned* ws = smem_u;                        // [128][WS_STRIDE] tf32
    unsigned* xs = smem_u + DH * WS_STRIDE;       // [64][XS_STRIDE]  tf32
    __shared__ float ssc[DH], ssh[DH];

    const int tid = threadIdx.x;

    if (mode) {
        if (tid < DH) {
            float mean = g_stats[0][tid] * (1.0f / NNODES);
            float var  = g_stats[0][DH + tid] * (1.0f / NNODES) - mean * mean;
            float sc   = gamma[tid] * rsqrtf(var + BN_EPS);
            ssc[tid] = sc;
            ssh[tid] = beta[tid] - mean * sc;
        }
        __syncthreads();
    }

    // ---- stage W (k-major) as tf32
    for (int i = tid; i < DH * DH / 4; i += GEMM_THREADS) {
        int k  = i >> 5;          // 32 float4 per row
        int c4 = (i & 31) << 2;
        float4 v = ((const float4*)W)[i];
        uint4 o;
        o.x = tf32_of(v.x); o.y = tf32_of(v.y);
        o.z = tf32_of(v.z); o.w = tf32_of(v.w);
        *(uint4*)(ws + k * WS_STRIDE + c4) = o;
    }

    // ---- stage X tile (fused BN+ReLU for mode 1) as tf32
    const int row0 = blk * TM;
    for (int i = tid; i < TM * DH / 4; i += GEMM_THREADS) {
        int r  = i >> 5;
        int c4 = (i & 31) << 2;
        float4 v = make_float4(0.f, 0.f, 0.f, 0.f);
        if (row0 + r < NNODES) {
            if (mode) {
                uint2 u = *(const uint2*)(g_aggb + (long)(row0 + r) * DH + c4);
                float2 f01 = __bfloat1622float2(*(__nv_bfloat162*)&u.x);
                float2 f23 = __bfloat1622float2(*(__nv_bfloat162*)&u.y);
                v.x = fmaxf(0.f, fmaf(f01.x, ssc[c4 + 0], ssh[c4 + 0]));
                v.y = fmaxf(0.f, fmaf(f01.y, ssc[c4 + 1], ssh[c4 + 1]));
                v.z = fmaxf(0.f, fmaf(f23.x, ssc[c4 + 2], ssh[c4 + 2]));
                v.w = fmaxf(0.f, fmaf(f23.y, ssc[c4 + 3], ssh[c4 + 3]));
            } else {
                v = *(const float4*)(Xext + (long)(row0 + r) * DH + c4);
            }
        }
        uint4 o;
        o.x = tf32_of(v.x); o.y = tf32_of(v.y);
        o.z = tf32_of(v.z); o.w = tf32_of(v.w);
        *(uint4*)(xs + r * XS_STRIDE + c4) = o;
    }
    __syncthreads();

    const int lane = tid & 31;
    const int warp = tid >> 5;
    const int mrow = (warp & 1) * 32;
    const int ncol = (warp >> 1) * 32;

    float acc[2][4][4];
#pragma unroll
    for (int mi = 0; mi < 2; mi++)
#pragma unroll
        for (int ni = 0; ni < 4; ni++)
#pragma unroll
            for (int j = 0; j < 4; j++) acc[mi][ni][j] = 0.f;

    const int ar = mrow + (lane >> 2);
    const int ak = lane & 3;
    const int bn = ncol + (lane >> 2);
    const int bk = lane & 3;

#pragma unroll 4
    for (int k0 = 0; k0 < DH; k0 += 8) {
        unsigned a[2][4], b[4][2];
#pragma unroll
        for (int mi = 0; mi < 2; mi++) {
            const unsigned* ab = xs + (ar + 16 * mi) * XS_STRIDE + k0 + ak;
            a[mi][0] = ab[0];
            a[mi][1] = ab[8 * XS_STRIDE];
            a[mi][2] = ab[4];
            a[mi][3] = ab[8 * XS_STRIDE + 4];
        }
#pragma unroll
        for (int ni = 0; ni < 4; ni++) {
            const unsigned* bb = ws + (k0 + bk) * WS_STRIDE + bn + 8 * ni;
            b[ni][0] = bb[0];
            b[ni][1] = bb[4 * WS_STRIDE];
        }
#pragma unroll
        for (int mi = 0; mi < 2; mi++)
#pragma unroll
            for (int ni = 0; ni < 4; ni++)
                MMA_TF32(acc[mi][ni], a[mi], b[ni]);
    }

    // ---- epilogue: bf16 pairs
#pragma unroll
    for (int mi = 0; mi < 2; mi++) {
        int r0 = row0 + mrow + 16 * mi + (lane >> 2);
        int r1 = r0 + 8;
#pragma unroll
        for (int ni = 0; ni < 4; ni++) {
            int cc = ncol + 8 * ni + 2 * (lane & 3);
            if (r0 < NNODES)
                *(__nv_bfloat162*)(g_hb + (long)r0 * DH + cc) =
                    __floats2bfloat162_rn(acc[mi][ni][0], acc[mi][ni][1]);
            if (r1 < NNODES)
                *(__nv_bfloat162*)(g_hb + (long)r1 * DH + cc) =
                    __floats2bfloat162_rn(acc[mi][ni][2], acc[mi][ni][3]);
        }
    }
}

// ---------------- fat kernel: gemm0 + interleaved grid-stride hist ----------
// every 8th block is a long-lived hist block -> runs concurrent with GEMMs
__global__ void gemm0_hist_kernel(const float* __restrict__ Xext,
                                  const float* __restrict__ W,
                                  const int* __restrict__ src,
                                  const int* __restrict__ dst,
                                  const float* __restrict__ ew) {
    const int bid = blockIdx.x;
    if ((bid & 7) == 7) {
        // histogram by dst + fused per-src weight sums (grid-stride)
        int b = bid >> 3;                 // 0..FAT_GROUPS-1
        const int stride = FAT_GROUPS * 256;
        for (int e = b * 256 + threadIdx.x; e < NEDGES; e += stride) {
            atomicAdd(&g_cnt[dst[e]], 1);
            atomicAdd(&g_s[src[e]], ew[e]);
        }
        return;
    }
    int gblk = (bid >> 3) * 7 + (bid & 7);
    if (gblk >= GRID_GEMM) return;
    gemm_body(Xext, W, 0, gblk, nullptr, nullptr);
}

__global__ void gemm1_kernel(const float* __restrict__ W,
                             const float* __restrict__ gamma,
                             const float* __restrict__ beta) {
    gemm_body(nullptr, W, 1, blockIdx.x, gamma, beta);
}

// ---------------- parallel segment allocation (order-free CSR) --------------
__global__ void alloc_kernel() {
    int n = blockIdx.x * blockDim.x + threadIdx.x;
    if (n < NNODES) {
        int c = g_cnt[n];
        int pos = atomicAdd(&g_total, c);
        g_rowptr[n] = pos;
        g_cnt[n] = pos;           // fill cursor; after fill == segment end
    }
}

// ---------------- fill CSR (single 8B store per edge) ------------------------
__global__ void fill_kernel(const int* __restrict__ src,
                            const int* __restrict__ dst,
                            const float* __restrict__ ew) {
    int e = blockIdx.x * blockDim.x + threadIdx.x;
    if (e < NEDGES) {
        int pos = atomicAdd(&g_cnt[dst[e]], 1);
        Edge ed; ed.s = src[e]; ed.w = ew[e];
        g_csr[pos] = ed;
    }
}

// ---------------- CSR gather-aggregate (bf16 in/out) with fused stats -------
__device__ __forceinline__ void acc_edge(float4& acc, uint2 u, float w) {
    float2 f01 = __bfloat1622float2(*(__nv_bfloat162*)&u.x);
    float2 f23 = __bfloat1622float2(*(__nv_bfloat162*)&u.y);
    acc.x = fmaf(w, f01.x, acc.x); acc.y = fmaf(w, f01.y, acc.y);
    acc.z = fmaf(w, f23.x, acc.z); acc.w = fmaf(w, f23.y, acc.w);
}

template <int Q>
__device__ __forceinline__ int acc_batch(int j, int end, int lane, float4& acc) {
    while (j + Q <= end) {
        Edge  e[Q];
        uint2 u[Q];
#pragma unroll
        for (int q = 0; q < Q; q++) e[q] = g_csr[j + q];
#pragma unroll
        for (int q = 0; q < Q; q++)
            u[q] = ((const uint2*)(g_hb + (long)e[q].s * DH))[lane];
#pragma unroll
        for (int q = 0; q < Q; q++) acc_edge(acc, u[q], e[q].w);
        j += Q;
    }
    return j;
}

__global__ void gather_kernel(int layer) {
    __shared__ float sred[8][DH];
    __shared__ float sred2[8][DH];
    const int tid = threadIdx.x;
    const int lane = tid & 31;
    const int warp = tid >> 5;

    float4 lsum = make_float4(0.f, 0.f, 0.f, 0.f);
    float4 lsq  = make_float4(0.f, 0.f, 0.f, 0.f);

    for (int n = blockIdx.x * 8 + warp; n < NNODES; n += gridDim.x * 8) {
        int beg = g_rowptr[n], end = g_cnt[n];   // cursor == segment end
        float4 acc = make_float4(0.f, 0.f, 0.f, 0.f);
        int j = beg;
        j = acc_batch<16>(j, end, lane, acc);    // 16 loads in flight
        j = acc_batch<8>(j, end, lane, acc);
        j = acc_batch<4>(j, end, lane, acc);
        j = acc_batch<1>(j, end, lane, acc);

        *(uint2*)(g_aggb + (long)n * DH + lane * 4) =
            *(uint2*)&(__nv_bfloat162[2]){
                __floats2bfloat162_rn(acc.x, acc.y),
                __floats2bfloat162_rn(acc.z, acc.w)};

        lsum.x += acc.x; lsum.y += acc.y; lsum.z += acc.z; lsum.w += acc.w;
        lsq.x = fmaf(acc.x, acc.x, lsq.x); lsq.y = fmaf(acc.y, acc.y, lsq.y);
        lsq.z = fmaf(acc.z, acc.z, lsq.z); lsq.w = fmaf(acc.w, acc.w, lsq.w);
    }

    sred[warp][lane * 4 + 0] = lsum.x;  sred2[warp][lane * 4 + 0] = lsq.x;
    sred[warp][lane * 4 + 1] = lsum.y;  sred2[warp][lane * 4 + 1] = lsq.y;
    sred[warp][lane * 4 + 2] = lsum.z;  sred2[warp][lane * 4 + 2] = lsq.z;
    sred[warp][lane * 4 + 3] = lsum.w;  sred2[warp][lane * 4 + 3] = lsq.w;
    __syncthreads();
    if (tid < DH) {
        float a = 0.f, b = 0.f;
#pragma unroll
        for (int w = 0; w < 8; w++) { a += sred[w][tid]; b += sred2[w][tid]; }
        atomicAdd(&g_stats[layer][tid], a);
        atomicAdd(&g_stats[layer][DH + tid], b);
    }
}

// ---------------- t = sum_n s[n] * relu(bn1(g_aggb[n,:])) -------------------
__global__ void treduce_kernel(const float* __restrict__ gamma,
                               const float* __restrict__ beta) {
    __shared__ float sred[8][DH];
    __shared__ float ssc[DH], ssh[DH];
    const int tid = threadIdx.x;
    const int lane = tid & 31;
    const int warp = tid >> 5;

    if (tid < DH) {
        float mean = g_stats[1][tid] * (1.0f / NNODES);
        float var  = g_stats[1][DH + tid] * (1.0f / NNODES) - mean * mean;
        float sc   = gamma[tid] * rsqrtf(var + BN_EPS);
        ssc[tid] = sc;
        ssh[tid] = beta[tid] - mean * sc;
    }
    __syncthreads();

    float4 sc4 = *(float4*)(ssc + lane * 4);
    float4 sh4 = *(float4*)(ssh + lane * 4);

    float4 lsum = make_float4(0.f, 0.f, 0.f, 0.f);
    for (int n = blockIdx.x * 8 + warp; n < NNODES; n += gridDim.x * 8) {
        float sn = g_s[n];
        uint2 u = *(const uint2*)(g_aggb + (long)n * DH + lane * 4);
        float2 f01 = __bfloat1622float2(*(__nv_bfloat162*)&u.x);
        float2 f23 = __bfloat1622float2(*(__nv_bfloat162*)&u.y);
        float v0 = fmaxf(0.f, fmaf(f01.x, sc4.x, sh4.x));
        float v1 = fmaxf(0.f, fmaf(f01.y, sc4.y, sh4.y));
        float v2 = fmaxf(0.f, fmaf(f23.x, sc4.z, sh4.z));
        float v3 = fmaxf(0.f, fmaf(f23.y, sc4.w, sh4.w));
        lsum.x = fmaf(sn, v0, lsum.x);
        lsum.y = fmaf(sn, v1, lsum.y);
        lsum.z = fmaf(sn, v2, lsum.z);
        lsum.w = fmaf(sn, v3, lsum.w);
    }

    sred[warp][lane * 4 + 0] = lsum.x;
    sred[warp][lane * 4 + 1] = lsum.y;
    sred[warp][lane * 4 + 2] = lsum.z;
    sred[warp][lane * 4 + 3] = lsum.w;
    __syncthreads();
    if (tid < DH) {
        float a = 0.f;
#pragma unroll
        for (int w = 0; w < 8; w++) a += sred[w][tid];
        atomicAdd(&g_t[tid], a);
    }
}

// ---------------- out = t @ W2 + N * b2 -------------------------------------
__global__ void final_kernel(const float* __restrict__ W2,
                             const float* __restrict__ b2,
                             float* __restrict__ out) {
    int o = threadIdx.x;   // 64 threads
    float acc = (float)NNODES * b2[o];
#pragma unroll 8
    for (int f = 0; f < DH; f++)
        acc = fmaf(g_t[f], W2[f * DOUT + o], acc);
    out[o] = acc;
}

// ---------------- launch ----------------------------------------------------
extern "C" void kernel_launch(void* const* d_in, const int* in_sizes, int n_in,
                              void* d_out, int out_size) {
    const float* nf     = (const float*)d_in[0];
    const int*   ei     = (const int*)  d_in[1];   // [2][E]
    const float* ew     = (const float*)d_in[2];
    const float* W0     = (const float*)d_in[3];
    const float* W1     = (const float*)d_in[5];
    const float* W2     = (const float*)d_in[7];
    const float* b2     = (const float*)d_in[8];
    const float* gamma0 = (const float*)d_in[9];
    const float* beta0  = (const float*)d_in[10];
    const float* gamma1 = (const float*)d_in[11];
    const float* beta1  = (const float*)d_in[12];
    const int* src = ei;
    const int* dst = ei + NEDGES;
    float* out = (float*)d_out;

    cudaFuncSetAttribute(gemm0_hist_kernel,
                         cudaFuncAttributeMaxDynamicSharedMemorySize,
                         (int)GEMM_SMEM);
    cudaFuncSetAttribute(gemm1_kernel,
                         cudaFuncAttributeMaxDynamicSharedMemorySize,
                         (int)GEMM_SMEM);

    // ---- init, then gemm0 with interleaved concurrent dst-histogram
    zero_init_kernel<<<(NNODES + 255) / 256, 256>>>();
    gemm0_hist_kernel<<<FAT_GRID, GEMM_THREADS, GEMM_SMEM>>>(
        nf, W0, src, dst, ew);

    // ---- order-free CSR segment allocation + fill
    alloc_kernel<<<(NNODES + 255) / 256, 256>>>();
    fill_kernel<<<FILL_BLOCKS, 256>>>(src, dst, ew);

    // ---- layer 0 aggregation (stats fused)
    gather_kernel<<<2048, 256>>>(0);

    // ---- layer 1: BN0+ReLU fused into GEMM tile load (inline BN params)
    gemm1_kernel<<<GRID_GEMM, GEMM_THREADS, GEMM_SMEM>>>(W1, gamma0, beta0);
    gather_kernel<<<2048, 256>>>(1);

    // ---- layer 2 collapsed: out = (s^T relu(bn1(agg1))) @ W2 + N*b2
    treduce_kernel<<<2048, 256>>>(gamma1, beta1);
    final_kernel<<<1, DOUT>>>(W2, b2, out);
}